// round 2
// baseline (speedup 1.0000x reference)
#include <cuda_runtime.h>
#include <math.h>

// Problem constants (fixed by setup_inputs)
#define NB   32          // batch
#define NA   3           // anchors
#define NC   20          // classes
#define NCH  25          // 5 + NC channels per anchor
#define NT   256         // number of targets
#define EPSF 1e-7f
#define THREADS 256
#define GRID    595      // 3 target blocks + 592 worker blocks (4/SM on 148 SMs)

// Persistent device accumulators (zero at module load; finalizer resets them
// after each launch so graph replays are deterministic).
__device__ double g_obj[3];
__device__ double g_box;
__device__ double g_cls;
__device__ unsigned int g_ticket;

__device__ __forceinline__ float softplusf(float x) {
    return fmaxf(x, 0.0f) + log1pf(expf(-fabsf(x)));
}
__device__ __forceinline__ float sigmoidf(float x) {
    return 1.0f / (1.0f + expf(-x));
}

// warp-shuffle + smem block reduce (one __syncthreads per call)
__device__ __forceinline__ double block_reduce_d(double v, double* sbuf) {
    int lane = threadIdx.x & 31;
    int wid  = threadIdx.x >> 5;
    #pragma unroll
    for (int s = 16; s > 0; s >>= 1)
        v += __shfl_down_sync(0xffffffffu, v, s);
    if (lane == 0) sbuf[wid] = v;
    __syncthreads();
    double r = 0.0;
    if (wid == 0) {
        r = (lane < (THREADS / 32)) ? sbuf[lane] : 0.0;
        #pragma unroll
        for (int s = 4; s > 0; s >>= 1)
            r += __shfl_down_sync(0xffffffffu, r, s);
    }
    return r;   // valid in thread 0 only
}

// ---------------------------------------------------------------------------
// Obj-plane partial sum, vectorized float4.
// Obj plane for (b,a) starts at ((b*NA + a)*NCH + 4)*HW, contiguous HW floats.
// ---------------------------------------------------------------------------
template <int H>
__device__ double obj_partial(const float* __restrict__ pred, int wb, int nworkers) {
    constexpr int HW  = H * H;
    constexpr int HW4 = HW / 4;
    constexpr int NV  = NB * NA * HW4;   // float4 count
    double s = 0.0;
    for (int i = wb * THREADS + threadIdx.x; i < NV; i += nworkers * THREADS) {
        int plane = i / HW4;             // const divisor
        int r     = i - plane * HW4;
        const float4* p = (const float4*)(pred + (size_t)(plane * NCH + 4) * HW);
        float4 x = __ldg(p + r);
        s += (double)(softplusf(x.x) + softplusf(x.y) +
                      softplusf(x.z) + softplusf(x.w));
    }
    return s;
}

// ---------------------------------------------------------------------------
// Target block: one thread per target, all anchors; box + cls losses and the
// obj correction (-x) at deduplicated target cells.
// ---------------------------------------------------------------------------
template <int H>
__device__ void target_work(const float* __restrict__ pred,
                            const float* __restrict__ tg,
                            int scale, double* sd, int* skey) {
    constexpr int W  = H;
    constexpr int HW = H * W;
    int n = threadIdx.x;   // n < NT == THREADS

    const float* t = tg + n * 6;
    int   bi  = (int)t[0];
    int   ci  = (int)t[1];
    float cx  = t[2] * (float)W;
    float cy  = t[3] * (float)H;
    int gi = (int)fminf(fmaxf(cx, 0.0f), (float)(W - 1));
    int gj = (int)fminf(fmaxf(cy, 0.0f), (float)(H - 1));

    // dedup key for obj_t .set() semantics (unique (b, gj, gi) cells)
    skey[n] = (bi * H + gj) * W + gi;
    __syncthreads();
    bool first = true;
    for (int j = 0; j < n; j++)
        if (skey[j] == skey[n]) { first = false; break; }

    float tx1 = t[2] - t[4] * 0.5f, ty1 = t[3] - t[5] * 0.5f;
    float tx2 = t[2] + t[4] * 0.5f, ty2 = t[3] + t[5] * 0.5f;
    float area_t = (tx2 - tx1) * (ty2 - ty1);

    float gif = (float)gi, gjf = (float)gj;
    float twh = t[4] * (float)W * 0.5f, thh = t[5] * (float)H * 0.5f;
    const float invW = 1.0f / (float)W, invH = 1.0f / (float)H;

    float box_l = 0.0f, cls_l = 0.0f, corr = 0.0f;

    size_t base_b = (size_t)bi * (NA * NCH) * HW + (size_t)gj * W + gi;
    #pragma unroll
    for (int a = 0; a < NA; a++) {
        size_t base = base_b + (size_t)(a * NCH) * HW;

        float x0 = __ldg(pred + base);
        float x1 = __ldg(pred + base + (size_t)HW);
        float sx = sigmoidf(x0);
        float sy = sigmoidf(x1);
        float px1 = (sx + gif - twh) * invW, py1 = (sy + gjf - thh) * invH;
        float px2 = (sx + gif + twh) * invW, py2 = (sy + gjf + thh) * invH;

        float ix1 = fmaxf(px1, tx1), iy1 = fmaxf(py1, ty1);
        float ix2 = fminf(px2, tx2), iy2 = fminf(py2, ty2);
        float inter = fmaxf(ix2 - ix1, 0.0f) * fmaxf(iy2 - iy1, 0.0f);
        float area_p = (px2 - px1) * (py2 - py1);
        float uni = area_p + area_t - inter + EPSF;
        float iou = inter / uni;

        float ex1 = fminf(px1, tx1), ey1 = fminf(py1, ty1);
        float ex2 = fmaxf(px2, tx2), ey2 = fmaxf(py2, ty2);
        float dcx = ex2 - ex1, dcy = ey2 - ey1;
        float c2 = dcx * dcx + dcy * dcy + EPSF;
        float mx = (px1 + px2) * 0.5f - (tx1 + tx2) * 0.5f;
        float my = (py1 + py2) * 0.5f - (ty1 + ty2) * 0.5f;
        float rho2 = mx * mx + my * my;

        float pw = fmaxf(px2 - px1, EPSF), ph = fmaxf(py2 - py1, EPSF);
        float tw = fmaxf(tx2 - tx1, EPSF), th = fmaxf(ty2 - ty1, EPSF);
        float dat = atanf(tw / th) - atanf(pw / ph);
        float v = (4.0f / (float)(M_PI * M_PI)) * dat * dat;
        float alpha = v / (1.0f - iou + v + EPSF);
        float ciou = iou - rho2 / c2 - alpha * v;
        box_l += 1.0f - ciou;

        if (first) corr -= __ldg(pred + base + (size_t)4 * HW);

        float acc = 0.0f;
        #pragma unroll
        for (int c = 0; c < NC; c++) {
            float x = __ldg(pred + base + (size_t)(5 + c) * HW);
            acc += softplusf(x);
            if (c == ci) acc -= x;    // softplus(-x) = softplus(x) - x
        }
        cls_l += acc * (1.0f / (float)NC);
    }

    double rb = block_reduce_d((double)box_l, sd); __syncthreads();
    double rc = block_reduce_d((double)cls_l, sd); __syncthreads();
    double ro = block_reduce_d((double)corr, sd);
    if (threadIdx.x == 0) {
        atomicAdd(&g_box, rb);
        atomicAdd(&g_cls, rc);
        atomicAdd(&g_obj[scale], ro);
    }
}

// ---------------------------------------------------------------------------
__global__ void __launch_bounds__(THREADS)
detection_loss_kernel(const float* __restrict__ p0, const float* __restrict__ p1,
                      const float* __restrict__ p2, const float* __restrict__ tg,
                      float* __restrict__ out) {
    __shared__ double sd[THREADS / 32];
    __shared__ int skey[NT];

    int bx = blockIdx.x;
    if (bx < 3) {
        if (bx == 0)      target_work<80>(p0, tg, 0, sd, skey);
        else if (bx == 1) target_work<40>(p1, tg, 1, sd, skey);
        else              target_work<20>(p2, tg, 2, sd, skey);
    } else {
        int wb = bx - 3;
        const int NW = GRID - 3;
        double s0 = obj_partial<80>(p0, wb, NW);
        double s1 = obj_partial<40>(p1, wb, NW);
        double s2 = obj_partial<20>(p2, wb, NW);
        double r0 = block_reduce_d(s0, sd); __syncthreads();
        double r1 = block_reduce_d(s1, sd); __syncthreads();
        double r2 = block_reduce_d(s2, sd);
        if (threadIdx.x == 0) {
            if (r0 != 0.0) atomicAdd(&g_obj[0], r0);
            if (r1 != 0.0) atomicAdd(&g_obj[1], r1);
            if (r2 != 0.0) atomicAdd(&g_obj[2], r2);
        }
    }

    if (threadIdx.x == 0) {
        __threadfence();
        unsigned old = atomicAdd(&g_ticket, 1u);
        if (old == (unsigned)(gridDim.x - 1)) {
            double o0 = atomicAdd(&g_obj[0], 0.0);
            double o1 = atomicAdd(&g_obj[1], 0.0);
            double o2 = atomicAdd(&g_obj[2], 0.0);
            double bsum = atomicAdd(&g_box, 0.0);
            double csum = atomicAdd(&g_cls, 0.0);

            double lo = o0 / (double)(NB * NA * 80 * 80)
                      + o1 / (double)(NB * NA * 40 * 40)
                      + o2 / (double)(NB * NA * 20 * 20);
            double num_targets = (double)(NT * NA * 3);   // 2304
            double lb = bsum / num_targets;
            double lc = csum / num_targets;
            double total = 0.05 * lb + 1.0 * lo + 0.5 * lc;

            out[0] = (float)total;
            out[1] = (float)lb;
            out[2] = (float)lo;
            out[3] = (float)lc;
            out[4] = 0.0f;

            g_obj[0] = 0.0; g_obj[1] = 0.0; g_obj[2] = 0.0;
            g_box = 0.0; g_cls = 0.0;
            __threadfence();
            atomicExch(&g_ticket, 0u);
        }
    }
}

extern "C" void kernel_launch(void* const* d_in, const int* in_sizes, int n_in,
                              void* d_out, int out_size) {
    const float* p0 = (const float*)d_in[0];
    const float* p1 = (const float*)d_in[1];
    const float* p2 = (const float*)d_in[2];
    const float* tg = (const float*)d_in[3];
    float* out = (float*)d_out;
    (void)in_sizes; (void)n_in; (void)out_size;

    detection_loss_kernel<<<GRID, THREADS>>>(p0, p1, p2, tg, out);
}

// round 3
// speedup vs baseline: 1.1248x; 1.1248x over previous
#include <cuda_runtime.h>
#include <math.h>

// Problem constants (fixed by setup_inputs)
#define NB   32
#define NA   3
#define NC   20
#define NCH  25
#define NT   256
#define EPSF 1e-7f
#define THREADS 256

#define TB_PER_SCALE 32          // 8 targets per target-block
#define NTB (3 * TB_PER_SCALE)   // 96 target blocks
#define NWB 256                  // obj-plane worker blocks
#define GRID (NTB + NWB)         // 352 total (single wave)

// obj mean weights: 1 / (NB*NA*H*W)
#define INV0 (1.0 / (double)(NB * NA * 80 * 80))
#define INV1 (1.0 / (double)(NB * NA * 40 * 40))
#define INV2 (1.0 / (double)(NB * NA * 20 * 20))

// Persistent accumulators (zeroed at load; finalizer resets per launch).
__device__ double g_lo;    // weighted obj loss (softplus sums + target corrections)
__device__ double g_box;
__device__ double g_cls;
__device__ unsigned int g_ticket;

__device__ __forceinline__ float softplusf(float x) {
    return fmaxf(x, 0.0f) + log1pf(expf(-fabsf(x)));
}
__device__ __forceinline__ float sigmoidf(float x) {
    return 1.0f / (1.0f + expf(-x));
}

__device__ __forceinline__ double block_reduce_d(double v, double* sbuf) {
    int lane = threadIdx.x & 31;
    int wid  = threadIdx.x >> 5;
    #pragma unroll
    for (int s = 16; s > 0; s >>= 1)
        v += __shfl_down_sync(0xffffffffu, v, s);
    if (lane == 0) sbuf[wid] = v;
    __syncthreads();
    double r = 0.0;
    if (wid == 0) {
        r = (lane < (THREADS / 32)) ? sbuf[lane] : 0.0;
        #pragma unroll
        for (int s = 4; s > 0; s >>= 1)
            r += __shfl_down_sync(0xffffffffu, r, s);
    }
    return r;   // valid in thread 0 only
}

// ---------------------------------------------------------------------------
// Obj-plane partial: sum softplus over one scale's obj channels (float4).
// ---------------------------------------------------------------------------
template <int H>
__device__ double obj_partial(const float* __restrict__ pred, int wb) {
    constexpr int HW  = H * H;
    constexpr int HW4 = HW / 4;
    constexpr int NV  = NB * NA * HW4;
    double s = 0.0;
    #pragma unroll 4
    for (int i = wb * THREADS + threadIdx.x; i < NV; i += NWB * THREADS) {
        int plane = i / HW4;
        int r     = i - plane * HW4;
        const float4* p = (const float4*)(pred + (size_t)(plane * NCH + 4) * HW);
        float4 x = __ldg(p + r);
        s += (double)(softplusf(x.x) + softplusf(x.y) +
                      softplusf(x.z) + softplusf(x.w));
    }
    return s;
}

// ---------------------------------------------------------------------------
// Target block: 8 targets (all anchors each) per block; 32 blocks per scale.
// Threads 0..7 do the gather work; all 256 threads build the dedup key table.
// ---------------------------------------------------------------------------
template <int H>
__device__ void target_work(const float* __restrict__ pred,
                            const float* __restrict__ tg,
                            int bis, double inv_scale) {
    constexpr int W  = H;
    constexpr int HW = H * W;
    __shared__ int skey[NT];

    int t = threadIdx.x;
    if (t < NT) {
        const float* tt = tg + t * 6;
        int bi = (int)tt[0];
        float cx = tt[2] * (float)W;
        float cy = tt[3] * (float)H;
        int gi = (int)fminf(fmaxf(cx, 0.0f), (float)(W - 1));
        int gj = (int)fminf(fmaxf(cy, 0.0f), (float)(H - 1));
        skey[t] = (bi * H + gj) * W + gi;
    }
    __syncthreads();

    double box_l = 0.0, cls_l = 0.0, corr = 0.0;

    if (t < 8) {
        int n = bis * 8 + t;
        const float* tt = tg + n * 6;
        int   bi  = (int)tt[0];
        int   ci  = (int)tt[1];
        float cx  = tt[2] * (float)W;
        float cy  = tt[3] * (float)H;
        int gi = (int)fminf(fmaxf(cx, 0.0f), (float)(W - 1));
        int gj = (int)fminf(fmaxf(cy, 0.0f), (float)(H - 1));

        int mykey = skey[n];
        bool first = true;
        for (int j = 0; j < n; j++)
            if (skey[j] == mykey) { first = false; break; }

        float tx1 = tt[2] - tt[4] * 0.5f, ty1 = tt[3] - tt[5] * 0.5f;
        float tx2 = tt[2] + tt[4] * 0.5f, ty2 = tt[3] + tt[5] * 0.5f;
        float area_t = (tx2 - tx1) * (ty2 - ty1);

        float gif = (float)gi, gjf = (float)gj;
        float twh = tt[4] * (float)W * 0.5f, thh = tt[5] * (float)H * 0.5f;
        const float invW = 1.0f / (float)W, invH = 1.0f / (float)H;

        float box_f = 0.0f, cls_f = 0.0f, corr_f = 0.0f;

        size_t base_b = (size_t)bi * (NA * NCH) * HW + (size_t)gj * W + gi;
        #pragma unroll
        for (int a = 0; a < NA; a++) {
            size_t base = base_b + (size_t)(a * NCH) * HW;

            float x0 = __ldg(pred + base);
            float x1 = __ldg(pred + base + (size_t)HW);
            float sx = sigmoidf(x0);
            float sy = sigmoidf(x1);
            float px1 = (sx + gif - twh) * invW, py1 = (sy + gjf - thh) * invH;
            float px2 = (sx + gif + twh) * invW, py2 = (sy + gjf + thh) * invH;

            float ix1 = fmaxf(px1, tx1), iy1 = fmaxf(py1, ty1);
            float ix2 = fminf(px2, tx2), iy2 = fminf(py2, ty2);
            float inter = fmaxf(ix2 - ix1, 0.0f) * fmaxf(iy2 - iy1, 0.0f);
            float area_p = (px2 - px1) * (py2 - py1);
            float uni = area_p + area_t - inter + EPSF;
            float iou = inter / uni;

            float ex1 = fminf(px1, tx1), ey1 = fminf(py1, ty1);
            float ex2 = fmaxf(px2, tx2), ey2 = fmaxf(py2, ty2);
            float dcx = ex2 - ex1, dcy = ey2 - ey1;
            float c2 = dcx * dcx + dcy * dcy + EPSF;
            float mx = (px1 + px2) * 0.5f - (tx1 + tx2) * 0.5f;
            float my = (py1 + py2) * 0.5f - (ty1 + ty2) * 0.5f;
            float rho2 = mx * mx + my * my;

            float pw = fmaxf(px2 - px1, EPSF), ph = fmaxf(py2 - py1, EPSF);
            float tw = fmaxf(tx2 - tx1, EPSF), th = fmaxf(ty2 - ty1, EPSF);
            float dat = atanf(tw / th) - atanf(pw / ph);
            float v = (4.0f / (float)(M_PI * M_PI)) * dat * dat;
            float alpha = v / (1.0f - iou + v + EPSF);
            float ciou = iou - rho2 / c2 - alpha * v;
            box_f += 1.0f - ciou;

            if (first) corr_f -= __ldg(pred + base + (size_t)4 * HW);

            float acc = 0.0f;
            #pragma unroll
            for (int c = 0; c < NC; c++) {
                float x = __ldg(pred + base + (size_t)(5 + c) * HW);
                acc += softplusf(x);
                if (c == ci) acc -= x;   // softplus(-x) = softplus(x) - x
            }
            cls_f += acc * (1.0f / (float)NC);
        }
        box_l = (double)box_f;
        cls_l = (double)cls_f;
        corr  = (double)corr_f * inv_scale;
    }

    // warp 0 lanes 0..7 carry the sums; lanes 8..31 are zero
    if (t < 32) {
        #pragma unroll
        for (int s = 16; s > 0; s >>= 1) {
            box_l += __shfl_down_sync(0xffffffffu, box_l, s);
            cls_l += __shfl_down_sync(0xffffffffu, cls_l, s);
            corr  += __shfl_down_sync(0xffffffffu, corr,  s);
        }
        if (t == 0) {
            atomicAdd(&g_box, box_l);
            atomicAdd(&g_cls, cls_l);
            atomicAdd(&g_lo,  corr);
        }
    }
}

// ---------------------------------------------------------------------------
__global__ void __launch_bounds__(THREADS)
detection_loss_kernel(const float* __restrict__ p0, const float* __restrict__ p1,
                      const float* __restrict__ p2, const float* __restrict__ tg,
                      float* __restrict__ out) {
    __shared__ double sd[THREADS / 32];

    int bx = blockIdx.x;
    if (bx < NTB) {
        int scale = bx / TB_PER_SCALE;
        int bis   = bx - scale * TB_PER_SCALE;
        if (scale == 0)      target_work<80>(p0, tg, bis, INV0);
        else if (scale == 1) target_work<40>(p1, tg, bis, INV1);
        else                 target_work<20>(p2, tg, bis, INV2);
    } else {
        int wb = bx - NTB;
        double acc = obj_partial<80>(p0, wb) * INV0
                   + obj_partial<40>(p1, wb) * INV1
                   + obj_partial<20>(p2, wb) * INV2;
        double r = block_reduce_d(acc, sd);
        if (threadIdx.x == 0 && r != 0.0) atomicAdd(&g_lo, r);
    }

    if (threadIdx.x == 0) {
        __threadfence();
        unsigned old = atomicAdd(&g_ticket, 1u);
        if (old == (unsigned)(gridDim.x - 1)) {
            double lo   = atomicAdd(&g_lo,  0.0);
            double bsum = atomicAdd(&g_box, 0.0);
            double csum = atomicAdd(&g_cls, 0.0);

            double num_targets = (double)(NT * NA * 3);   // 2304
            double lb = bsum / num_targets;
            double lc = csum / num_targets;
            double total = 0.05 * lb + 1.0 * lo + 0.5 * lc;

            out[0] = (float)total;
            out[1] = (float)lb;
            out[2] = (float)lo;
            out[3] = (float)lc;
            out[4] = 0.0f;

            g_lo = 0.0; g_box = 0.0; g_cls = 0.0;
            __threadfence();
            atomicExch(&g_ticket, 0u);
        }
    }
}

extern "C" void kernel_launch(void* const* d_in, const int* in_sizes, int n_in,
                              void* d_out, int out_size) {
    const float* p0 = (const float*)d_in[0];
    const float* p1 = (const float*)d_in[1];
    const float* p2 = (const float*)d_in[2];
    const float* tg = (const float*)d_in[3];
    float* out = (float*)d_out;
    (void)in_sizes; (void)n_in; (void)out_size;

    detection_loss_kernel<<<GRID, THREADS>>>(p0, p1, p2, tg, out);
}

// round 6
// speedup vs baseline: 2.2324x; 1.9847x over previous
#include <cuda_runtime.h>
#include <math.h>

// R4 design, restructured source (two prior submissions hit container-level
// infra failures with no kernel signal; same algorithm, fresh translation unit).

#define NB   32
#define NA   3
#define NC   20
#define NCH  25
#define NT   256
#define EPSF 1e-7f
#define THREADS 256

#define PAIRS_PER_SCALE 768                // NT * NA
#define TBLK  288                          // blocks carrying 8 warp-pairs each
#define GRID  296                          // 2 blocks/SM * 148 SMs
#define NWB   GRID

#define INV0 (1.0 / (double)(NB * NA * 80 * 80))
#define INV1 (1.0 / (double)(NB * NA * 40 * 40))
#define INV2 (1.0 / (double)(NB * NA * 20 * 20))

__device__ double g_acc[3];                // 0: lo (weighted), 1: box, 2: cls
__device__ unsigned int g_ticket;

__device__ __forceinline__ float fast_softplus(float x) {
    return fmaxf(x, 0.0f) + __logf(1.0f + __expf(-fabsf(x)));
}
__device__ __forceinline__ float fast_sigmoid(float x) {
    return __frcp_rn(1.0f + __expf(-x));
}

// ---------------------------------------------------------------------------
// Obj partial: grid-strided float4 sum of softplus over obj channels.
// ---------------------------------------------------------------------------
template <int H>
__device__ __forceinline__ float obj_partial(const float* __restrict__ pred, int wb) {
    constexpr int HW  = H * H;
    constexpr int HW4 = HW / 4;
    constexpr int NV  = NB * NA * HW4;
    float s = 0.0f;
    #pragma unroll 1
    for (int i = wb * THREADS + threadIdx.x; i < NV; i += NWB * THREADS) {
        int plane = i / HW4;
        int r     = i - plane * HW4;
        float4 x = __ldg((const float4*)(pred + (size_t)(plane * NCH + 4) * HW) + r);
        s += fast_softplus(x.x) + fast_softplus(x.y)
           + fast_softplus(x.z) + fast_softplus(x.w);
    }
    return s;
}

// ---------------------------------------------------------------------------
// Warp handles one (target, anchor) pair; lane c loads channel c.
// Outputs valid on lane 0 (box, cls); corr uniform.
// ---------------------------------------------------------------------------
template <int H>
__device__ __forceinline__ void pair_losses(const float* __restrict__ pred,
                                            const float* __restrict__ tg,
                                            const int* __restrict__ skey,
                                            int n, int a,
                                            float& box, float& cls, float& corr) {
    constexpr int W  = H;
    constexpr int HW = H * W;
    const unsigned FULL = 0xffffffffu;
    const int lane = threadIdx.x & 31;

    const float* tt = tg + n * 6;
    float t2 = __ldg(tt + 2), t3 = __ldg(tt + 3);
    float t4 = __ldg(tt + 4), t5 = __ldg(tt + 5);
    int bi = (int)__ldg(tt + 0);
    int ci = (int)__ldg(tt + 1);
    int gi = (int)fminf(fmaxf(t2 * (float)W, 0.0f), (float)(W - 1));
    int gj = (int)fminf(fmaxf(t3 * (float)H, 0.0f), (float)(H - 1));

    // dedup against earlier targets mapping to same (b, gj, gi) cell
    int mykey = skey[n];
    bool dup = false;
    for (int j = lane; j < n; j += 32)
        dup |= (skey[j] == mykey);
    bool first = !__any_sync(FULL, dup);

    size_t base = (size_t)(bi * (NA * NCH) + a * NCH) * HW + (size_t)(gj * W + gi);
    float x = 0.0f;
    if (lane < NCH) x = __ldg(pred + base + (size_t)lane * HW);

    float x0 = __shfl_sync(FULL, x, 0);
    float x1 = __shfl_sync(FULL, x, 1);
    float x4 = __shfl_sync(FULL, x, 4);
    corr = first ? -x4 : 0.0f;

    // cls BCE on lanes 5..24
    float cl = 0.0f;
    if (lane >= 5 && lane < 25) {
        cl = fast_softplus(x);
        if (lane == ci + 5) cl -= x;         // softplus(-x) = softplus(x) - x
    }
    #pragma unroll
    for (int s = 16; s > 0; s >>= 1)
        cl += __shfl_down_sync(FULL, cl, s);
    cls = cl * (1.0f / (float)NC);

    // CIoU (uniform math; every lane computes, lane 0's value used)
    float tx1 = t2 - t4 * 0.5f, ty1 = t3 - t5 * 0.5f;
    float tx2 = t2 + t4 * 0.5f, ty2 = t3 + t5 * 0.5f;
    float area_t = (tx2 - tx1) * (ty2 - ty1);
    float gif = (float)gi, gjf = (float)gj;
    float twh = t4 * (float)W * 0.5f, thh = t5 * (float)H * 0.5f;
    const float invW = 1.0f / (float)W, invH = 1.0f / (float)H;

    float sx = fast_sigmoid(x0), sy = fast_sigmoid(x1);
    float px1 = (sx + gif - twh) * invW, py1 = (sy + gjf - thh) * invH;
    float px2 = (sx + gif + twh) * invW, py2 = (sy + gjf + thh) * invH;

    float inter = fmaxf(fminf(px2, tx2) - fmaxf(px1, tx1), 0.0f)
                * fmaxf(fminf(py2, ty2) - fmaxf(py1, ty1), 0.0f);
    float area_p = (px2 - px1) * (py2 - py1);
    float iou = inter / (area_p + area_t - inter + EPSF);

    float dcx = fmaxf(px2, tx2) - fminf(px1, tx1);
    float dcy = fmaxf(py2, ty2) - fminf(py1, ty1);
    float c2 = dcx * dcx + dcy * dcy + EPSF;
    float mx = (px1 + px2 - tx1 - tx2) * 0.5f;
    float my = (py1 + py2 - ty1 - ty2) * 0.5f;
    float rho2 = mx * mx + my * my;

    float pw = fmaxf(px2 - px1, EPSF), ph = fmaxf(py2 - py1, EPSF);
    float tw = fmaxf(tx2 - tx1, EPSF), th = fmaxf(ty2 - ty1, EPSF);
    float dat = atanf(tw / th) - atanf(pw / ph);
    float v = (4.0f / (float)(M_PI * M_PI)) * dat * dat;
    float alpha = v / (1.0f - iou + v + EPSF);
    box = 1.0f - (iou - rho2 / c2 - alpha * v);
}

// ---------------------------------------------------------------------------
__global__ void __launch_bounds__(THREADS)
detection_loss_kernel(const float* __restrict__ p0, const float* __restrict__ p1,
                      const float* __restrict__ p2, const float* __restrict__ tg,
                      float* __restrict__ out) {
    __shared__ int    skey[NT];
    __shared__ float  sbox[8];
    __shared__ float  scls[8];
    __shared__ double sred[8];

    const int bx   = blockIdx.x;
    const int tid  = threadIdx.x;
    const int wid  = tid >> 5;
    const int lane = tid & 31;

    // obj partial over all three scales (every block)
    double acc = (double)obj_partial<80>(p0, bx) * INV0
               + (double)obj_partial<40>(p1, bx) * INV1
               + (double)obj_partial<20>(p2, bx) * INV2;

    sbox[wid] = 0.0f;
    scls[wid] = 0.0f;

    if (bx < TBLK) {
        int scale = bx / 96;
        int H = (scale == 0) ? 80 : (scale == 1) ? 40 : 20;
        const float* pred = (scale == 0) ? p0 : (scale == 1) ? p1 : p2;

        // per-scale dedup keys for all 256 targets
        {
            const float* tt = tg + tid * 6;
            int b  = (int)__ldg(tt + 0);
            int gi = (int)fminf(fmaxf(__ldg(tt + 2) * (float)H, 0.0f), (float)(H - 1));
            int gj = (int)fminf(fmaxf(__ldg(tt + 3) * (float)H, 0.0f), (float)(H - 1));
            skey[tid] = (b * H + gj) * H + gi;
        }
        __syncthreads();

        int r = bx * 8 + wid - scale * PAIRS_PER_SCALE;   // 0..767
        int n = r / 3;
        int a = r - 3 * n;

        float box, cls, corr;
        if (scale == 0)      pair_losses<80>(pred, tg, skey, n, a, box, cls, corr);
        else if (scale == 1) pair_losses<40>(pred, tg, skey, n, a, box, cls, corr);
        else                 pair_losses<20>(pred, tg, skey, n, a, box, cls, corr);

        if (lane == 0) {
            sbox[wid] = box;
            scls[wid] = cls;
            double inv = (scale == 0) ? INV0 : (scale == 1) ? INV1 : INV2;
            acc += (double)corr * inv;
        }
    }

    // block reduce of the double accumulator
    #pragma unroll
    for (int s = 16; s > 0; s >>= 1)
        acc += __shfl_down_sync(0xffffffffu, acc, s);
    if (lane == 0) sred[wid] = acc;
    __syncthreads();

    if (tid == 0) {
        double r_obj = 0.0;
        float bsum = 0.0f, csum = 0.0f;
        #pragma unroll
        for (int w = 0; w < 8; w++) {
            r_obj += sred[w];
            bsum  += sbox[w];
            csum  += scls[w];
        }
        atomicAdd(&g_acc[0], r_obj);
        if (bsum != 0.0f) atomicAdd(&g_acc[1], (double)bsum);
        if (csum != 0.0f) atomicAdd(&g_acc[2], (double)csum);

        __threadfence();
        unsigned old = atomicAdd(&g_ticket, 1u);
        if (old == (unsigned)(GRID - 1)) {
            volatile double* ga = g_acc;
            double lo = ga[0];
            double lb = ga[1] * (1.0 / 2304.0);   // NT*NA*3
            double lc = ga[2] * (1.0 / 2304.0);
            double total = 0.05 * lb + lo + 0.5 * lc;

            out[0] = (float)total;
            out[1] = (float)lb;
            out[2] = (float)lo;
            out[3] = (float)lc;
            out[4] = 0.0f;

            g_acc[0] = 0.0; g_acc[1] = 0.0; g_acc[2] = 0.0;
            __threadfence();
            atomicExch(&g_ticket, 0u);
        }
    }
}

extern "C" void kernel_launch(void* const* d_in, const int* in_sizes, int n_in,
                              void* d_out, int out_size) {
    const float* p0 = (const float*)d_in[0];
    const float* p1 = (const float*)d_in[1];
    const float* p2 = (const float*)d_in[2];
    const float* tg = (const float*)d_in[3];
    float* out = (float*)d_out;
    (void)in_sizes; (void)n_in; (void)out_size;

    detection_loss_kernel<<<GRID, THREADS>>>(p0, p1, p2, tg, out);
}